// round 1
// baseline (speedup 1.0000x reference)
#include <cuda_runtime.h>
#include <math.h>

#define B_    8192
#define D_    1024
#define H_    4096
#define E_    8
#define NSLOT (B_ * 2)
#define RMAX  17408   // 16384 + 8*128 tile padding

// ---------------- scratch (device globals: allocation-free) ----------------
__device__ float g_h[(size_t)RMAX * H_];   // gelu(fc1) activations, gathered rows
__device__ float g_o[(size_t)RMAX * D_];   // fc2 outputs, gathered rows
__device__ int   g_tok[RMAX];              // gathered row -> token id
__device__ int   g_pos[NSLOT];             // (b,k) -> gathered row
__device__ int   g_eidx[NSLOT];            // (b,k) -> expert
__device__ float g_gval[NSLOT];            // (b,k) -> gate value
__device__ int   g_cnt[E_];
__device__ int   g_cur[E_];
__device__ int   g_off[E_ + 1];
__device__ float g_imp[E_];

// ---------------- 1) gating: logits, top-2, softmax over top-2 -------------
__global__ void gating_kernel(const float* __restrict__ x,
                              const float* __restrict__ wg)
{
    __shared__ float ws[E_ * D_];
    for (int i = threadIdx.x; i < E_ * D_; i += blockDim.x) ws[i] = wg[i];
    __syncthreads();

    const int warp = threadIdx.x >> 5, lane = threadIdx.x & 31;
    const int b = blockIdx.x * 8 + warp;
    const float* xr = x + (size_t)b * D_;

    float acc[E_];
#pragma unroll
    for (int e = 0; e < E_; e++) acc[e] = 0.f;

    for (int d = lane; d < D_; d += 32) {
        float xv = xr[d];
#pragma unroll
        for (int e = 0; e < E_; e++) acc[e] = fmaf(xv, ws[e * D_ + d], acc[e]);
    }
#pragma unroll
    for (int e = 0; e < E_; e++) {
#pragma unroll
        for (int o = 16; o; o >>= 1) acc[e] += __shfl_down_sync(0xffffffffu, acc[e], o);
    }
    if (lane == 0) {
        int i0 = 0; float v0 = acc[0];
#pragma unroll
        for (int e = 1; e < E_; e++) if (acc[e] > v0) { v0 = acc[e]; i0 = e; }
        int i1 = -1; float v1 = -INFINITY;
#pragma unroll
        for (int e = 0; e < E_; e++) if (e != i0 && acc[e] > v1) { v1 = acc[e]; i1 = e; }
        float t  = expf(v1 - v0);          // <= 1
        float gA = 1.f / (1.f + t);
        float gB = t / (1.f + t);
        g_eidx[b * 2 + 0] = i0;  g_eidx[b * 2 + 1] = i1;
        g_gval[b * 2 + 0] = gA;  g_gval[b * 2 + 1] = gB;
    }
}

// ---------------- 2) deterministic per-expert stats ------------------------
__global__ void expert_stats_kernel()
{
    const int e = blockIdx.x;
    const int tid = threadIdx.x;
    float imp = 0.f; int cnt = 0;
    for (int i = tid; i < NSLOT; i += 256) {
        if (g_eidx[i] == e) { imp += g_gval[i]; cnt++; }
    }
    __shared__ float simp[256];
    __shared__ int   scnt[256];
    simp[tid] = imp; scnt[tid] = cnt;
    __syncthreads();
    for (int s = 128; s; s >>= 1) {
        if (tid < s) { simp[tid] += simp[tid + s]; scnt[tid] += scnt[tid + s]; }
        __syncthreads();
    }
    if (tid == 0) { g_imp[e] = simp[0]; g_cnt[e] = scnt[0]; }
}

// ---------------- 3) offsets scan + aux loss --------------------------------
__global__ void scan_loss_kernel(float* __restrict__ out)
{
    if (threadIdx.x == 0 && blockIdx.x == 0) {
        int off = 0;
        for (int e = 0; e < E_; e++) {
            g_off[e] = off; g_cur[e] = off;
            off += ((g_cnt[e] + 127) >> 7) << 7;
        }
        g_off[E_] = off;

        float mi = 0.f, ml = 0.f;
        for (int e = 0; e < E_; e++) { mi += g_imp[e]; ml += (float)g_cnt[e]; }
        mi *= (1.f / E_); ml *= (1.f / E_);
        float vi = 0.f, vl = 0.f;
        for (int e = 0; e < E_; e++) {
            float di = g_imp[e] - mi;        vi += di * di;
            float dl = (float)g_cnt[e] - ml; vl += dl * dl;
        }
        vi *= (1.f / (E_ - 1)); vl *= (1.f / (E_ - 1));
        float loss = (vi / (mi * mi + 1e-10f) + vl / (ml * ml + 1e-10f)) * 0.01f;
        out[(size_t)B_ * D_] = loss;
    }
}

// ---------------- 4) scatter token slots into expert segments ---------------
__global__ void scatter_kernel()
{
    int i = blockIdx.x * blockDim.x + threadIdx.x;
    if (i < NSLOT) {
        int e = g_eidx[i];
        int pos = atomicAdd(&g_cur[e], 1);
        g_tok[pos] = i >> 1;
        g_pos[i] = pos;
    }
}

// ---------------- 5/6) grouped GEMM (128x128x16 fp32 SIMT) ------------------
// PHASE1: C[r,n] = gelu( gather(x)[r,:] . fc1_w[e][n,:] + fc1_b[e][n] ) -> g_h
// PHASE2: C[r,n] =        g_h[r,:]      . fc2_w[e][n,:] + fc2_b[e][n]   -> g_o
template<int N, int KD, bool PHASE1>
__global__ __launch_bounds__(256, 2)
void gemm_kernel(const float* __restrict__ X,
                 const float* __restrict__ W,
                 const float* __restrict__ bias)
{
    __shared__ float As[16][128];
    __shared__ float Bs[16][128];

    const int row0 = blockIdx.x * 128;
    if (row0 >= g_off[E_]) return;

    int e = 0;
#pragma unroll
    for (int i = 0; i < E_; i++) if (row0 >= g_off[i + 1]) e = i + 1;
    const int rowEnd = g_off[e] + g_cnt[e];

    const float* We = W + (size_t)e * N * KD;
    const int n0 = blockIdx.y * 128;

    const int tid = threadIdx.x;
    const int ar0 = tid >> 2;           // 0..63
    const int ar1 = ar0 + 64;
    const int akq = (tid & 3) * 4;      // k sub-offset 0,4,8,12

    const float* pA0;
    const float* pA1;
    if (PHASE1) {
        int r0 = row0 + ar0, r1 = row0 + ar1;
        int t0 = (r0 < rowEnd) ? g_tok[r0] : 0;
        int t1 = (r1 < rowEnd) ? g_tok[r1] : 0;
        pA0 = X + (size_t)t0 * KD + akq;
        pA1 = X + (size_t)t1 * KD + akq;
    } else {
        pA0 = g_h + (size_t)(row0 + ar0) * KD + akq;
        pA1 = g_h + (size_t)(row0 + ar1) * KD + akq;
    }
    const float* pB0 = We + (size_t)(n0 + ar0) * KD + akq;
    const float* pB1 = We + (size_t)(n0 + ar1) * KD + akq;

    const int tx = tid & 15, ty = tid >> 4;
    float acc[8][8] = {};

    for (int k0 = 0; k0 < KD; k0 += 16) {
        float4 a0 = *(const float4*)(pA0 + k0);
        float4 a1 = *(const float4*)(pA1 + k0);
        float4 b0 = *(const float4*)(pB0 + k0);
        float4 b1 = *(const float4*)(pB1 + k0);
        __syncthreads();
        As[akq + 0][ar0] = a0.x; As[akq + 1][ar0] = a0.y; As[akq + 2][ar0] = a0.z; As[akq + 3][ar0] = a0.w;
        As[akq + 0][ar1] = a1.x; As[akq + 1][ar1] = a1.y; As[akq + 2][ar1] = a1.z; As[akq + 3][ar1] = a1.w;
        Bs[akq + 0][ar0] = b0.x; Bs[akq + 1][ar0] = b0.y; Bs[akq + 2][ar0] = b0.z; Bs[akq + 3][ar0] = b0.w;
        Bs[akq + 0][ar1] = b1.x; Bs[akq + 1][ar1] = b1.y; Bs[akq + 2][ar1] = b1.z; Bs[akq + 3][ar1] = b1.w;
        __syncthreads();
#pragma unroll
        for (int k = 0; k < 16; k++) {
            float av[8], bv[8];
            *(float4*)&av[0] = *(const float4*)&As[k][ty * 8];
            *(float4*)&av[4] = *(const float4*)&As[k][ty * 8 + 4];
            *(float4*)&bv[0] = *(const float4*)&Bs[k][tx * 8];
            *(float4*)&bv[4] = *(const float4*)&Bs[k][tx * 8 + 4];
#pragma unroll
            for (int i = 0; i < 8; i++)
#pragma unroll
                for (int j = 0; j < 8; j++)
                    acc[i][j] = fmaf(av[i], bv[j], acc[i][j]);
        }
    }

    float bvec[8];
#pragma unroll
    for (int j = 0; j < 8; j++) bvec[j] = bias[(size_t)e * N + n0 + tx * 8 + j];

    float* Cbase = PHASE1 ? g_h : g_o;
#pragma unroll
    for (int i = 0; i < 8; i++) {
        int r = row0 + ty * 8 + i;
        if (r < rowEnd) {
            float v[8];
#pragma unroll
            for (int j = 0; j < 8; j++) {
                float t = acc[i][j] + bvec[j];
                if (PHASE1) t = 0.5f * t * (1.0f + erff(t * 0.7071067811865475f));
                v[j] = t;
            }
            float* cp = Cbase + (size_t)r * N + n0 + tx * 8;
            *(float4*)cp       = make_float4(v[0], v[1], v[2], v[3]);
            *(float4*)(cp + 4) = make_float4(v[4], v[5], v[6], v[7]);
        }
    }
}

// ---------------- 7) dual softmax + combine + log ---------------------------
__global__ void combine_kernel(float* __restrict__ out)
{
    __shared__ float s0[D_], s1[D_];
    __shared__ float r0[8], r1[8];

    const int b = blockIdx.x;
    const int tid = threadIdx.x;
    const int lane = tid & 31, warp = tid >> 5;

    const int   p0 = g_pos[b * 2 + 0], p1 = g_pos[b * 2 + 1];
    const float gg0 = g_gval[b * 2 + 0], gg1 = g_gval[b * 2 + 1];
    const float* q0 = g_o + (size_t)p0 * D_;
    const float* q1 = g_o + (size_t)p1 * D_;

    float m0 = -INFINITY, m1 = -INFINITY;
    for (int d = tid; d < D_; d += 256) {
        float v0 = q0[d], v1 = q1[d];
        s0[d] = v0; s1[d] = v1;
        m0 = fmaxf(m0, v0); m1 = fmaxf(m1, v1);
    }
#pragma unroll
    for (int o = 16; o; o >>= 1) {
        m0 = fmaxf(m0, __shfl_down_sync(0xffffffffu, m0, o));
        m1 = fmaxf(m1, __shfl_down_sync(0xffffffffu, m1, o));
    }
    if (lane == 0) { r0[warp] = m0; r1[warp] = m1; }
    __syncthreads();
    if (tid == 0) {
        float a = r0[0], c = r1[0];
        for (int i = 1; i < 8; i++) { a = fmaxf(a, r0[i]); c = fmaxf(c, r1[i]); }
        r0[0] = a; r1[0] = c;
    }
    __syncthreads();
    m0 = r0[0]; m1 = r1[0];

    float e0 = 0.f, e1 = 0.f;
    for (int d = tid; d < D_; d += 256) {
        e0 += expf(s0[d] - m0);
        e1 += expf(s1[d] - m1);
    }
#pragma unroll
    for (int o = 16; o; o >>= 1) {
        e0 += __shfl_down_sync(0xffffffffu, e0, o);
        e1 += __shfl_down_sync(0xffffffffu, e1, o);
    }
    __syncthreads();                 // before reusing r0/r1
    if (lane == 0) { r0[warp] = e0; r1[warp] = e1; }
    __syncthreads();
    if (tid == 0) {
        float a = 0.f, c = 0.f;
        for (int i = 0; i < 8; i++) { a += r0[i]; c += r1[i]; }
        r0[0] = a; r1[0] = c;
    }
    __syncthreads();
    const float c0 = gg0 / r0[0];
    const float c1 = gg1 / r1[0];

    for (int d = tid; d < D_; d += 256) {
        float c = c0 * expf(s0[d] - m0) + c1 * expf(s1[d] - m1);
        if (c == 0.f) c = 2.2204460492503131e-16f;
        out[(size_t)b * D_ + d] = logf(c);
    }
}

// ---------------- launch ----------------------------------------------------
extern "C" void kernel_launch(void* const* d_in, const int* in_sizes, int n_in,
                              void* d_out, int out_size)
{
    const float* x    = (const float*)d_in[0];
    const float* wg   = (const float*)d_in[1];
    const float* fc1w = (const float*)d_in[2];
    const float* fc1b = (const float*)d_in[3];
    const float* fc2w = (const float*)d_in[4];
    const float* fc2b = (const float*)d_in[5];
    float* out = (float*)d_out;

    gating_kernel<<<B_ / 8, 256>>>(x, wg);
    expert_stats_kernel<<<E_, 256>>>();
    scan_loss_kernel<<<1, 32>>>(out);
    scatter_kernel<<<(NSLOT + 255) / 256, 256>>>();

    dim3 g1(RMAX / 128, H_ / 128);   // 136 x 32
    gemm_kernel<H_, D_, true><<<g1, 256>>>(x, fc1w, fc1b);

    dim3 g2(RMAX / 128, D_ / 128);   // 136 x 8
    gemm_kernel<D_, H_, false><<<g2, 256>>>(nullptr, fc2w, fc2b);

    combine_kernel<<<B_, 256>>>(out);
}

// round 3
// speedup vs baseline: 2.3994x; 2.3994x over previous
#include <cuda_runtime.h>
#include <cuda_bf16.h>
#include <math.h>
#include <stdint.h>

#define B_    8192
#define D_    1024
#define H_    4096
#define E_    8
#define NSLOT (B_ * 2)
#define RMAX  17408   // 16384 + 8*128 tile padding

// ---------------- scratch (device globals: allocation-free) ----------------
__device__ __align__(128) __nv_bfloat16 g_hhi[(size_t)RMAX * H_];
__device__ __align__(128) __nv_bfloat16 g_hlo[(size_t)RMAX * H_];
__device__ __align__(128) float g_o[(size_t)RMAX * D_];
__device__ int   g_tok[RMAX];
__device__ int   g_pos[NSLOT];
__device__ int   g_eidx[NSLOT];
__device__ float g_gval[NSLOT];
__device__ int   g_cnt[E_];
__device__ int   g_cur[E_];
__device__ int   g_off[E_ + 1];
__device__ float g_imp[E_];

// ---------------- helpers ----------------------------------------------------
__device__ __forceinline__ uint32_t smem_u32(const void* p) {
    uint32_t a;
    asm("{ .reg .u64 t; cvta.to.shared.u64 t, %1; cvt.u32.u64 %0, t; }" : "=r"(a) : "l"(p));
    return a;
}
__device__ __forceinline__ void ldmx4(uint32_t& r0, uint32_t& r1, uint32_t& r2, uint32_t& r3,
                                      uint32_t addr) {
    asm volatile("ldmatrix.sync.aligned.m8n8.x4.shared.b16 {%0,%1,%2,%3}, [%4];"
                 : "=r"(r0), "=r"(r1), "=r"(r2), "=r"(r3) : "r"(addr));
}
__device__ __forceinline__ void mma16816(float* c, const uint32_t* a, uint32_t b0, uint32_t b1) {
    asm volatile("mma.sync.aligned.m16n8k16.row.col.f32.bf16.bf16.f32 "
                 "{%0,%1,%2,%3}, {%4,%5,%6,%7}, {%8,%9}, {%0,%1,%2,%3};"
                 : "+f"(c[0]), "+f"(c[1]), "+f"(c[2]), "+f"(c[3])
                 : "r"(a[0]), "r"(a[1]), "r"(a[2]), "r"(a[3]), "r"(b0), "r"(b1));
}
// split 4 fp32 -> packed bf16 hi pair-words and lo pair-words
__device__ __forceinline__ void split4(float4 v, uint32_t& h0, uint32_t& h1,
                                       uint32_t& l0, uint32_t& l1) {
    __nv_bfloat16 a = __float2bfloat16(v.x), b = __float2bfloat16(v.y);
    __nv_bfloat16 c = __float2bfloat16(v.z), d = __float2bfloat16(v.w);
    __nv_bfloat16 e = __float2bfloat16(v.x - __bfloat162float(a));
    __nv_bfloat16 f = __float2bfloat16(v.y - __bfloat162float(b));
    __nv_bfloat16 g = __float2bfloat16(v.z - __bfloat162float(c));
    __nv_bfloat16 h = __float2bfloat16(v.w - __bfloat162float(d));
    h0 = (uint32_t)__bfloat16_as_ushort(a) | ((uint32_t)__bfloat16_as_ushort(b) << 16);
    h1 = (uint32_t)__bfloat16_as_ushort(c) | ((uint32_t)__bfloat16_as_ushort(d) << 16);
    l0 = (uint32_t)__bfloat16_as_ushort(e) | ((uint32_t)__bfloat16_as_ushort(f) << 16);
    l1 = (uint32_t)__bfloat16_as_ushort(g) | ((uint32_t)__bfloat16_as_ushort(h) << 16);
}

// ---------------- 1) gating --------------------------------------------------
__global__ void gating_kernel(const float* __restrict__ x,
                              const float* __restrict__ wg)
{
    __shared__ float ws[E_ * D_];
    for (int i = threadIdx.x; i < E_ * D_; i += blockDim.x) ws[i] = wg[i];
    __syncthreads();

    const int warp = threadIdx.x >> 5, lane = threadIdx.x & 31;
    const int b = blockIdx.x * 8 + warp;
    const float* xr = x + (size_t)b * D_;

    float acc[E_];
#pragma unroll
    for (int e = 0; e < E_; e++) acc[e] = 0.f;
    for (int d = lane; d < D_; d += 32) {
        float xv = xr[d];
#pragma unroll
        for (int e = 0; e < E_; e++) acc[e] = fmaf(xv, ws[e * D_ + d], acc[e]);
    }
#pragma unroll
    for (int e = 0; e < E_; e++) {
#pragma unroll
        for (int o = 16; o; o >>= 1) acc[e] += __shfl_down_sync(0xffffffffu, acc[e], o);
    }
    if (lane == 0) {
        int i0 = 0; float v0 = acc[0];
#pragma unroll
        for (int e = 1; e < E_; e++) if (acc[e] > v0) { v0 = acc[e]; i0 = e; }
        int i1 = -1; float v1 = -INFINITY;
#pragma unroll
        for (int e = 0; e < E_; e++) if (e != i0 && acc[e] > v1) { v1 = acc[e]; i1 = e; }
        float t  = expf(v1 - v0);
        float gA = 1.f / (1.f + t);
        float gB = t / (1.f + t);
        g_eidx[b * 2 + 0] = i0;  g_eidx[b * 2 + 1] = i1;
        g_gval[b * 2 + 0] = gA;  g_gval[b * 2 + 1] = gB;
    }
}

// ---------------- 2) per-expert stats ----------------------------------------
__global__ void expert_stats_kernel()
{
    const int e = blockIdx.x;
    const int tid = threadIdx.x;
    float imp = 0.f; int cnt = 0;
    for (int i = tid; i < NSLOT; i += 256)
        if (g_eidx[i] == e) { imp += g_gval[i]; cnt++; }
    __shared__ float simp[256];
    __shared__ int   scnt[256];
    simp[tid] = imp; scnt[tid] = cnt;
    __syncthreads();
    for (int s = 128; s; s >>= 1) {
        if (tid < s) { simp[tid] += simp[tid + s]; scnt[tid] += scnt[tid + s]; }
        __syncthreads();
    }
    if (tid == 0) { g_imp[e] = simp[0]; g_cnt[e] = scnt[0]; }
}

// ---------------- 3) scan + loss ----------------------------------------------
__global__ void scan_loss_kernel(float* __restrict__ out)
{
    if (threadIdx.x == 0 && blockIdx.x == 0) {
        int off = 0;
        for (int e = 0; e < E_; e++) {
            g_off[e] = off; g_cur[e] = off;
            off += ((g_cnt[e] + 127) >> 7) << 7;
        }
        g_off[E_] = off;
        float mi = 0.f, ml = 0.f;
        for (int e = 0; e < E_; e++) { mi += g_imp[e]; ml += (float)g_cnt[e]; }
        mi *= (1.f / E_); ml *= (1.f / E_);
        float vi = 0.f, vl = 0.f;
        for (int e = 0; e < E_; e++) {
            float di = g_imp[e] - mi;        vi += di * di;
            float dl = (float)g_cnt[e] - ml; vl += dl * dl;
        }
        vi *= (1.f / (E_ - 1)); vl *= (1.f / (E_ - 1));
        out[(size_t)B_ * D_] = (vi / (mi * mi + 1e-10f) + vl / (ml * ml + 1e-10f)) * 0.01f;
    }
}

// ---------------- 4) scatter ---------------------------------------------------
__global__ void scatter_kernel()
{
    int i = blockIdx.x * blockDim.x + threadIdx.x;
    if (i < NSLOT) {
        int e = g_eidx[i];
        int pos = atomicAdd(&g_cur[e], 1);
        g_tok[pos] = i >> 1;
        g_pos[i] = pos;
    }
}

// ---------------- 5/6) grouped GEMM, mma.sync bf16 split-3 --------------------
// CTA tile 128x128, K-step 32. Warp grid 4(m) x 2(n), warp tile 32x64.
// SMEM: padded row stride 40 halves (80B) -> ldmatrix conflict-free.
#define LDS_ 40

template<int NFULL, int KDIM, bool PH1>
__global__ __launch_bounds__(256, 2)
void gemm_mma(const float* __restrict__ X, const float* __restrict__ W,
              const float* __restrict__ bias)
{
    __shared__ __nv_bfloat16 As[2][128 * LDS_];   // [0]=hi [1]=lo
    __shared__ __nv_bfloat16 Bs[2][128 * LDS_];

    const int row0 = blockIdx.x * 128;
    if (row0 >= g_off[E_]) return;

    int e = 0;
#pragma unroll
    for (int i = 0; i < E_; i++) if (row0 >= g_off[i + 1]) e = i + 1;
    const int rowEnd = g_off[e] + g_cnt[e];

    const int tid = threadIdx.x;
    const int w = tid >> 5, lane = tid & 31;
    const int wm = w & 3, wn = w >> 2;
    const int n0 = blockIdx.y * 128;
    const float* We = W + (size_t)e * NFULL * KDIM;

    // per-thread global load coords: idx = tid + i*256 -> row=idx>>3, q=idx&7
    const float* pB[4];
    const float* pA1[4];
    const __nv_bfloat16* pAh[4];
    const __nv_bfloat16* pAl[4];
    uint32_t sOff[4];
#pragma unroll
    for (int i = 0; i < 4; i++) {
        int idx = tid + i * 256;
        int row = idx >> 3, q = idx & 7;
        sOff[i] = row * LDS_ + q * 4;                 // halves
        pB[i] = We + (size_t)(n0 + row) * KDIM + q * 4;
        if (PH1) {
            int tok = g_tok[row0 + row];
            pA1[i] = X + (size_t)tok * KDIM + q * 4;
        } else {
            pAh[i] = g_hhi + (size_t)(row0 + row) * KDIM + q * 4;
            pAl[i] = g_hlo + (size_t)(row0 + row) * KDIM + q * 4;
        }
    }

    float acc[2][8][4];
#pragma unroll
    for (int a = 0; a < 2; a++)
#pragma unroll
        for (int b = 0; b < 8; b++)
#pragma unroll
            for (int c = 0; c < 4; c++) acc[a][b][c] = 0.f;

    // prefetch regs
    float4 fB[4]; float4 fA[4]; uint2 uAh[4], uAl[4];
#pragma unroll
    for (int i = 0; i < 4; i++) {
        fB[i] = __ldg((const float4*)pB[i]);
        if (PH1) fA[i] = __ldg((const float4*)pA1[i]);
        else { uAh[i] = __ldg((const uint2*)pAh[i]); uAl[i] = __ldg((const uint2*)pAl[i]); }
    }

    const uint32_t sbA0 = smem_u32(&As[0][0]);
    const uint32_t sbA1 = smem_u32(&As[1][0]);
    const uint32_t sbB0 = smem_u32(&Bs[0][0]);
    const uint32_t sbB1 = smem_u32(&Bs[1][0]);

    const int NC = KDIM / 32;
    for (int c = 0; c < NC; c++) {
        __syncthreads();
        // store prefetched regs -> smem (split fp32 into hi/lo bf16)
#pragma unroll
        for (int i = 0; i < 4; i++) {
            uint32_t h0, h1, l0, l1;
            split4(fB[i], h0, h1, l0, l1);
            *(uint2*)&Bs[0][sOff[i]] = make_uint2(h0, h1);
            *(uint2*)&Bs[1][sOff[i]] = make_uint2(l0, l1);
            if (PH1) {
                split4(fA[i], h0, h1, l0, l1);
                *(uint2*)&As[0][sOff[i]] = make_uint2(h0, h1);
                *(uint2*)&As[1][sOff[i]] = make_uint2(l0, l1);
            } else {
                *(uint2*)&As[0][sOff[i]] = uAh[i];
                *(uint2*)&As[1][sOff[i]] = uAl[i];
            }
        }
        __syncthreads();

        // prefetch next iter
        if (c + 1 < NC) {
            int k1 = (c + 1) * 32;
#pragma unroll
            for (int i = 0; i < 4; i++) {
                fB[i] = __ldg((const float4*)(pB[i] + k1));
                if (PH1) fA[i] = __ldg((const float4*)(pA1[i] + k1));
                else { uAh[i] = __ldg((const uint2*)(pAh[i] + k1)); uAl[i] = __ldg((const uint2*)(pAl[i] + k1)); }
            }
        }

        // compute: 2 k16 sub-steps
#pragma unroll
        for (int ks = 0; ks < 2; ks++) {
            const int kk = ks * 16;
            // A fragments (hi & lo) for 2 m16 frags
            uint32_t aH[2][4], aL[2][4];
            uint32_t aoff = ((wm * 32 + (lane & 15)) * LDS_ + kk + ((lane >> 4) << 3)) * 2;
#pragma unroll
            for (int mf = 0; mf < 2; mf++) {
                ldmx4(aH[mf][0], aH[mf][1], aH[mf][2], aH[mf][3], sbA0 + aoff + mf * 16 * LDS_ * 2);
                ldmx4(aL[mf][0], aL[mf][1], aL[mf][2], aL[mf][3], sbA1 + aoff + mf * 16 * LDS_ * 2);
            }
            // B fragments: 4 x (ldmatrix.x4 covering two n8 frags)
            uint32_t boff = ((wn * 64 + ((lane >> 4) << 3) + (lane & 7)) * LDS_
                             + kk + (((lane >> 3) & 1) << 3)) * 2;
#pragma unroll
            for (int j2 = 0; j2 < 4; j2++) {
                uint32_t bh[4], bl[4];
                ldmx4(bh[0], bh[1], bh[2], bh[3], sbB0 + boff + j2 * 16 * LDS_ * 2);
                ldmx4(bl[0], bl[1], bl[2], bl[3], sbB1 + boff + j2 * 16 * LDS_ * 2);
#pragma unroll
                for (int mf = 0; mf < 2; mf++) {
#pragma unroll
                    for (int nf = 0; nf < 2; nf++) {
                        float* cc = acc[mf][j2 * 2 + nf];
                        mma16816(cc, aH[mf], bh[2 * nf], bh[2 * nf + 1]);   // hi*hi
                        mma16816(cc, aH[mf], bl[2 * nf], bl[2 * nf + 1]);   // hi*lo
                        mma16816(cc, aL[mf], bh[2 * nf], bh[2 * nf + 1]);   // lo*hi
                    }
                }
            }
        }
    }

    // ---- epilogue ----
    const int g = lane >> 2, cpair = lane & 3;
#pragma unroll
    for (int mf = 0; mf < 2; mf++) {
        int rA = row0 + wm * 32 + mf * 16 + g;
        int rB = rA + 8;
        bool vA = rA < rowEnd, vB = rB < rowEnd;
#pragma unroll
        for (int nf = 0; nf < 8; nf++) {
            int col = n0 + wn * 64 + nf * 8 + 2 * cpair;
            float b0 = __ldg(&bias[(size_t)e * NFULL + col]);
            float b1 = __ldg(&bias[(size_t)e * NFULL + col + 1]);
            float* cc = acc[mf][nf];
            if (PH1) {
#pragma unroll
                for (int half = 0; half < 2; half++) {
                    bool v = half ? vB : vA;
                    if (!v) continue;
                    int r = half ? rB : rA;
                    float v0 = cc[half * 2 + 0] + b0;
                    float v1 = cc[half * 2 + 1] + b1;
                    v0 = 0.5f * v0 * (1.0f + erff(v0 * 0.7071067811865476f));
                    v1 = 0.5f * v1 * (1.0f + erff(v1 * 0.7071067811865476f));
                    __nv_bfloat16 h0 = __float2bfloat16(v0);
                    __nv_bfloat16 h1 = __float2bfloat16(v1);
                    __nv_bfloat16 e0 = __float2bfloat16(v0 - __bfloat162float(h0));
                    __nv_bfloat16 e1 = __float2bfloat16(v1 - __bfloat162float(h1));
                    uint32_t hw = (uint32_t)__bfloat16_as_ushort(h0) | ((uint32_t)__bfloat16_as_ushort(h1) << 16);
                    uint32_t lw = (uint32_t)__bfloat16_as_ushort(e0) | ((uint32_t)__bfloat16_as_ushort(e1) << 16);
                    size_t go = (size_t)r * H_ + col;
                    *(uint32_t*)&g_hhi[go] = hw;
                    *(uint32_t*)&g_hlo[go] = lw;
                }
            } else {
                if (vA) *(float2*)&g_o[(size_t)rA * D_ + col] = make_float2(cc[0] + b0, cc[1] + b1);
                if (vB) *(float2*)&g_o[(size_t)rB * D_ + col] = make_float2(cc[2] + b0, cc[3] + b1);
            }
        }
    }
}

// ---------------- 7) dual softmax + combine + log -----------------------------
__global__ void combine_kernel(float* __restrict__ out)
{
    __shared__ float s0[D_], s1[D_];
    __shared__ float r0[8], r1[8];

    const int b = blockIdx.x;
    const int tid = threadIdx.x;
    const int lane = tid & 31, warp = tid >> 5;

    const int   p0 = g_pos[b * 2 + 0], p1 = g_pos[b * 2 + 1];
    const float gg0 = g_gval[b * 2 + 0], gg1 = g_gval[b * 2 + 1];
    const float* q0 = g_o + (size_t)p0 * D_;
    const float* q1 = g_o + (size_t)p1 * D_;

    float m0 = -INFINITY, m1 = -INFINITY;
    for (int d = tid; d < D_; d += 256) {
        float v0 = q0[d], v1 = q1[d];
        s0[d] = v0; s1[d] = v1;
        m0 = fmaxf(m0, v0); m1 = fmaxf(m1, v1);
    }
#pragma unroll
    for (int o = 16; o; o >>= 1) {
        m0 = fmaxf(m0, __shfl_down_sync(0xffffffffu, m0, o));
        m1 = fmaxf(m1, __shfl_down_sync(0xffffffffu, m1, o));
    }
    if (lane == 0) { r0[warp] = m0; r1[warp] = m1; }
    __syncthreads();
    if (tid == 0) {
        float a = r0[0], c = r1[0];
        for (int i = 1; i < 8; i++) { a = fmaxf(a, r0[i]); c = fmaxf(c, r1[i]); }
        r0[0] = a; r1[0] = c;
    }
    __syncthreads();
    m0 = r0[0]; m1 = r1[0];

    float e0 = 0.f, e1 = 0.f;
    for (int d = tid; d < D_; d += 256) {
        e0 += expf(s0[d] - m0);
        e1 += expf(s1[d] - m1);
    }
#pragma unroll
    for (int o = 16; o; o >>= 1) {
        e0 += __shfl_down_sync(0xffffffffu, e0, o);
        e1 += __shfl_down_sync(0xffffffffu, e1, o);
    }
    __syncthreads();
    if (lane == 0) { r0[warp] = e0; r1[warp] = e1; }
    __syncthreads();
    if (tid == 0) {
        float a = 0.f, c = 0.f;
        for (int i = 0; i < 8; i++) { a += r0[i]; c += r1[i]; }
        r0[0] = a; r1[0] = c;
    }
    __syncthreads();
    const float c0 = gg0 / r0[0];
    const float c1 = gg1 / r1[0];

    for (int d = tid; d < D_; d += 256) {
        float c = c0 * expf(s0[d] - m0) + c1 * expf(s1[d] - m1);
        if (c == 0.f) c = 2.2204460492503131e-16f;
        out[(size_t)b * D_ + d] = logf(c);
    }
}

// ---------------- launch --------------------------------------------------------
extern "C" void kernel_launch(void* const* d_in, const int* in_sizes, int n_in,
                              void* d_out, int out_size)
{
    const float* x    = (const float*)d_in[0];
    const float* wg   = (const float*)d_in[1];
    const float* fc1w = (const float*)d_in[2];
    const float* fc1b = (const float*)d_in[3];
    const float* fc2w = (const float*)d_in[4];
    const float* fc2b = (const float*)d_in[5];
    float* out = (float*)d_out;

    gating_kernel<<<B_ / 8, 256>>>(x, wg);
    expert_stats_kernel<<<E_, 256>>>();
    scan_loss_kernel<<<1, 32>>>(out);
    scatter_kernel<<<(NSLOT + 255) / 256, 256>>>();

    gemm_mma<H_, D_, true><<<dim3(RMAX / 128, H_ / 128), 256>>>(x, fc1w, fc1b);
    gemm_mma<D_, H_, false><<<dim3(RMAX / 128, D_ / 128), 256>>>(nullptr, fc2w, fc2b);

    combine_kernel<<<B_, 256>>>(out);
}

// round 4
// speedup vs baseline: 4.8864x; 2.0365x over previous
#include <cuda_runtime.h>
#include <cuda_fp16.h>
#include <math.h>
#include <stdint.h>

#define B_    8192
#define D_    1024
#define H_    4096
#define E_    8
#define NSLOT (B_ * 2)
#define RMAX  17408   // 16384 + 8*128 tile padding

// ---------------- scratch (device globals: allocation-free) ----------------
__device__ __align__(128) __half g_h[(size_t)RMAX * H_];   // gelu(fc1), fp16
__device__ __align__(128) float  g_o[(size_t)RMAX * D_];
__device__ int   g_tok[RMAX];
__device__ int   g_pos[NSLOT];
__device__ int   g_eidx[NSLOT];
__device__ float g_gval[NSLOT];
__device__ int   g_cnt[E_];
__device__ int   g_cur[E_];
__device__ int   g_off[E_ + 1];
__device__ float g_imp[E_];

// ---------------- helpers ----------------------------------------------------
__device__ __forceinline__ uint32_t smem_u32(const void* p) {
    uint32_t a;
    asm("{ .reg .u64 t; cvta.to.shared.u64 t, %1; cvt.u32.u64 %0, t; }" : "=r"(a) : "l"(p));
    return a;
}
__device__ __forceinline__ void ldmx4(uint32_t& r0, uint32_t& r1, uint32_t& r2, uint32_t& r3,
                                      uint32_t addr) {
    asm volatile("ldmatrix.sync.aligned.m8n8.x4.shared.b16 {%0,%1,%2,%3}, [%4];"
                 : "=r"(r0), "=r"(r1), "=r"(r2), "=r"(r3) : "r"(addr));
}
__device__ __forceinline__ void mma16816(float* c, const uint32_t* a, uint32_t b0, uint32_t b1) {
    asm volatile("mma.sync.aligned.m16n8k16.row.col.f32.f16.f16.f32 "
                 "{%0,%1,%2,%3}, {%4,%5,%6,%7}, {%8,%9}, {%0,%1,%2,%3};"
                 : "+f"(c[0]), "+f"(c[1]), "+f"(c[2]), "+f"(c[3])
                 : "r"(a[0]), "r"(a[1]), "r"(a[2]), "r"(a[3]), "r"(b0), "r"(b1));
}
__device__ __forceinline__ uint2 pack4h(float4 v) {
    __half2 p0 = __floats2half2_rn(v.x, v.y);
    __half2 p1 = __floats2half2_rn(v.z, v.w);
    return make_uint2(*(uint32_t*)&p0, *(uint32_t*)&p1);
}

// ---------------- 1) gating --------------------------------------------------
__global__ void gating_kernel(const float* __restrict__ x,
                              const float* __restrict__ wg)
{
    __shared__ float ws[E_ * D_];
    for (int i = threadIdx.x; i < E_ * D_; i += blockDim.x) ws[i] = wg[i];
    __syncthreads();

    const int warp = threadIdx.x >> 5, lane = threadIdx.x & 31;
    const int b = blockIdx.x * 8 + warp;
    const float* xr = x + (size_t)b * D_;

    float acc[E_];
#pragma unroll
    for (int e = 0; e < E_; e++) acc[e] = 0.f;
    for (int d = lane; d < D_; d += 32) {
        float xv = xr[d];
#pragma unroll
        for (int e = 0; e < E_; e++) acc[e] = fmaf(xv, ws[e * D_ + d], acc[e]);
    }
#pragma unroll
    for (int e = 0; e < E_; e++) {
#pragma unroll
        for (int o = 16; o; o >>= 1) acc[e] += __shfl_down_sync(0xffffffffu, acc[e], o);
    }
    if (lane == 0) {
        int i0 = 0; float v0 = acc[0];
#pragma unroll
        for (int e = 1; e < E_; e++) if (acc[e] > v0) { v0 = acc[e]; i0 = e; }
        int i1 = -1; float v1 = -INFINITY;
#pragma unroll
        for (int e = 0; e < E_; e++) if (e != i0 && acc[e] > v1) { v1 = acc[e]; i1 = e; }
        float t  = expf(v1 - v0);
        float gA = 1.f / (1.f + t);
        float gB = t / (1.f + t);
        g_eidx[b * 2 + 0] = i0;  g_eidx[b * 2 + 1] = i1;
        g_gval[b * 2 + 0] = gA;  g_gval[b * 2 + 1] = gB;
    }
}

// ---------------- 2) per-expert stats ----------------------------------------
__global__ void expert_stats_kernel()
{
    const int e = blockIdx.x;
    const int tid = threadIdx.x;
    float imp = 0.f; int cnt = 0;
    for (int i = tid; i < NSLOT; i += 256)
        if (g_eidx[i] == e) { imp += g_gval[i]; cnt++; }
    __shared__ float simp[256];
    __shared__ int   scnt[256];
    simp[tid] = imp; scnt[tid] = cnt;
    __syncthreads();
    for (int s = 128; s; s >>= 1) {
        if (tid < s) { simp[tid] += simp[tid + s]; scnt[tid] += scnt[tid + s]; }
        __syncthreads();
    }
    if (tid == 0) { g_imp[e] = simp[0]; g_cnt[e] = scnt[0]; }
}

// ---------------- 3) scan + loss ----------------------------------------------
__global__ void scan_loss_kernel(float* __restrict__ out)
{
    if (threadIdx.x == 0 && blockIdx.x == 0) {
        int off = 0;
        for (int e = 0; e < E_; e++) {
            g_off[e] = off; g_cur[e] = off;
            off += ((g_cnt[e] + 127) >> 7) << 7;
        }
        g_off[E_] = off;
        float mi = 0.f, ml = 0.f;
        for (int e = 0; e < E_; e++) { mi += g_imp[e]; ml += (float)g_cnt[e]; }
        mi *= (1.f / E_); ml *= (1.f / E_);
        float vi = 0.f, vl = 0.f;
        for (int e = 0; e < E_; e++) {
            float di = g_imp[e] - mi;        vi += di * di;
            float dl = (float)g_cnt[e] - ml; vl += dl * dl;
        }
        vi *= (1.f / (E_ - 1)); vl *= (1.f / (E_ - 1));
        out[(size_t)B_ * D_] = (vi / (mi * mi + 1e-10f) + vl / (ml * ml + 1e-10f)) * 0.01f;
    }
}

// ---------------- 4) scatter ---------------------------------------------------
__global__ void scatter_kernel()
{
    int i = blockIdx.x * blockDim.x + threadIdx.x;
    if (i < NSLOT) {
        int e = g_eidx[i];
        int pos = atomicAdd(&g_cur[e], 1);
        g_tok[pos] = i >> 1;
        g_pos[i] = pos;
    }
}

// ---------------- 5/6) grouped GEMM, mma.sync fp16 single-term ----------------
// CTA tile 128x128, K-step 32. Warp grid 4(m) x 2(n), warp tile 32x64.
// SMEM padded row stride 40 halves -> ldmatrix conflict-free.
#define LDS_ 40

template<int NFULL, int KDIM, bool PH1>
__global__ __launch_bounds__(256, 2)
void gemm_mma(const float* __restrict__ X, const float* __restrict__ W,
              const float* __restrict__ bias)
{
    __shared__ __half As[128 * LDS_];
    __shared__ __half Bs[128 * LDS_];

    const int row0 = blockIdx.x * 128;
    if (row0 >= g_off[E_]) return;

    int e = 0;
#pragma unroll
    for (int i = 0; i < E_; i++) if (row0 >= g_off[i + 1]) e = i + 1;
    const int rowEnd = g_off[e] + g_cnt[e];

    const int tid = threadIdx.x;
    const int w = tid >> 5, lane = tid & 31;
    const int wm = w & 3, wn = w >> 2;
    const int n0 = blockIdx.y * 128;
    const float* We = W + (size_t)e * NFULL * KDIM;

    // per-thread global-load coords: idx = tid + i*256 -> row=idx>>3, q=idx&7
    const float*  pB[4];
    const float*  pA1[4];
    const __half* pA2[4];
    uint32_t sOff[4];
#pragma unroll
    for (int i = 0; i < 4; i++) {
        int idx = tid + i * 256;
        int row = idx >> 3, q = idx & 7;
        sOff[i] = row * LDS_ + q * 4;                 // halves
        pB[i] = We + (size_t)(n0 + row) * KDIM + q * 4;
        if (PH1) {
            int tok = g_tok[row0 + row];
            pA1[i] = X + (size_t)tok * KDIM + q * 4;
        } else {
            pA2[i] = g_h + (size_t)(row0 + row) * KDIM + q * 4;
        }
    }

    float acc[2][8][4];
#pragma unroll
    for (int a = 0; a < 2; a++)
#pragma unroll
        for (int b = 0; b < 8; b++)
#pragma unroll
            for (int c = 0; c < 4; c++) acc[a][b][c] = 0.f;

    // prefetch regs
    float4 fB[4]; float4 fA[4]; uint2 uA[4];
#pragma unroll
    for (int i = 0; i < 4; i++) {
        fB[i] = __ldg((const float4*)pB[i]);
        if (PH1) fA[i] = __ldg((const float4*)pA1[i]);
        else     uA[i] = __ldg((const uint2*)pA2[i]);
    }

    const uint32_t sbA = smem_u32(&As[0]);
    const uint32_t sbB = smem_u32(&Bs[0]);

    const int NC = KDIM / 32;
    for (int c = 0; c < NC; c++) {
        __syncthreads();
#pragma unroll
        for (int i = 0; i < 4; i++) {
            *(uint2*)&Bs[sOff[i]] = pack4h(fB[i]);
            if (PH1) *(uint2*)&As[sOff[i]] = pack4h(fA[i]);
            else     *(uint2*)&As[sOff[i]] = uA[i];
        }
        __syncthreads();

        if (c + 1 < NC) {
            int k1 = (c + 1) * 32;
#pragma unroll
            for (int i = 0; i < 4; i++) {
                fB[i] = __ldg((const float4*)(pB[i] + k1));
                if (PH1) fA[i] = __ldg((const float4*)(pA1[i] + k1));
                else     uA[i] = __ldg((const uint2*)(pA2[i] + k1));
            }
        }

#pragma unroll
        for (int ks = 0; ks < 2; ks++) {
            const int kk = ks * 16;
            uint32_t aF[2][4];
            uint32_t aoff = ((wm * 32 + (lane & 15)) * LDS_ + kk + ((lane >> 4) << 3)) * 2;
#pragma unroll
            for (int mf = 0; mf < 2; mf++)
                ldmx4(aF[mf][0], aF[mf][1], aF[mf][2], aF[mf][3], sbA + aoff + mf * 16 * LDS_ * 2);

            uint32_t boff = ((wn * 64 + ((lane >> 4) << 3) + (lane & 7)) * LDS_
                             + kk + (((lane >> 3) & 1) << 3)) * 2;
#pragma unroll
            for (int j2 = 0; j2 < 4; j2++) {
                uint32_t bf[4];
                ldmx4(bf[0], bf[1], bf[2], bf[3], sbB + boff + j2 * 16 * LDS_ * 2);
#pragma unroll
                for (int mf = 0; mf < 2; mf++) {
#pragma unroll
                    for (int nf = 0; nf < 2; nf++)
                        mma16816(acc[mf][j2 * 2 + nf], aF[mf], bf[2 * nf], bf[2 * nf + 1]);
                }
            }
        }
    }

    // ---- epilogue ----
    const int g = lane >> 2, cpair = lane & 3;
#pragma unroll
    for (int mf = 0; mf < 2; mf++) {
        int rA = row0 + wm * 32 + mf * 16 + g;
        int rB = rA + 8;
        bool vA = rA < rowEnd, vB = rB < rowEnd;
#pragma unroll
        for (int nf = 0; nf < 8; nf++) {
            int col = n0 + wn * 64 + nf * 8 + 2 * cpair;
            float b0 = __ldg(&bias[(size_t)e * NFULL + col]);
            float b1 = __ldg(&bias[(size_t)e * NFULL + col + 1]);
            float* cc = acc[mf][nf];
            if (PH1) {
#pragma unroll
                for (int half = 0; half < 2; half++) {
                    bool v = half ? vB : vA;
                    if (!v) continue;
                    int r = half ? rB : rA;
                    float v0 = cc[half * 2 + 0] + b0;
                    float v1 = cc[half * 2 + 1] + b1;
                    v0 = 0.5f * v0 * (1.0f + erff(v0 * 0.7071067811865476f));
                    v1 = 0.5f * v1 * (1.0f + erff(v1 * 0.7071067811865476f));
                    __half2 hw = __floats2half2_rn(v0, v1);
                    *(uint32_t*)&g_h[(size_t)r * H_ + col] = *(uint32_t*)&hw;
                }
            } else {
                if (vA) *(float2*)&g_o[(size_t)rA * D_ + col] = make_float2(cc[0] + b0, cc[1] + b1);
                if (vB) *(float2*)&g_o[(size_t)rB * D_ + col] = make_float2(cc[2] + b0, cc[3] + b1);
            }
        }
    }
}

// ---------------- 7) dual softmax + combine + log -----------------------------
__global__ void combine_kernel(float* __restrict__ out)
{
    __shared__ float s0[D_], s1[D_];
    __shared__ float r0[8], r1[8];

    const int b = blockIdx.x;
    const int tid = threadIdx.x;
    const int lane = tid & 31, warp = tid >> 5;

    const int   p0 = g_pos[b * 2 + 0], p1 = g_pos[b * 2 + 1];
    const float gg0 = g_gval[b * 2 + 0], gg1 = g_gval[b * 2 + 1];
    const float* q0 = g_o + (size_t)p0 * D_;
    const float* q1 = g_o + (size_t)p1 * D_;

    float m0 = -INFINITY, m1 = -INFINITY;
    for (int d = tid; d < D_; d += 256) {
        float v0 = q0[d], v1 = q1[d];
        s0[d] = v0; s1[d] = v1;
        m0 = fmaxf(m0, v0); m1 = fmaxf(m1, v1);
    }
#pragma unroll
    for (int o = 16; o; o >>= 1) {
        m0 = fmaxf(m0, __shfl_down_sync(0xffffffffu, m0, o));
        m1 = fmaxf(m1, __shfl_down_sync(0xffffffffu, m1, o));
    }
    if (lane == 0) { r0[warp] = m0; r1[warp] = m1; }
    __syncthreads();
    if (tid == 0) {
        float a = r0[0], c = r1[0];
        for (int i = 1; i < 8; i++) { a = fmaxf(a, r0[i]); c = fmaxf(c, r1[i]); }
        r0[0] = a; r1[0] = c;
    }
    __syncthreads();
    m0 = r0[0]; m1 = r1[0];

    float e0 = 0.f, e1 = 0.f;
    for (int d = tid; d < D_; d += 256) {
        e0 += expf(s0[d] - m0);
        e1 += expf(s1[d] - m1);
    }
#pragma unroll
    for (int o = 16; o; o >>= 1) {
        e0 += __shfl_down_sync(0xffffffffu, e0, o);
        e1 += __shfl_down_sync(0xffffffffu, e1, o);
    }
    __syncthreads();
    if (lane == 0) { r0[warp] = e0; r1[warp] = e1; }
    __syncthreads();
    if (tid == 0) {
        float a = 0.f, c = 0.f;
        for (int i = 0; i < 8; i++) { a += r0[i]; c += r1[i]; }
        r0[0] = a; r1[0] = c;
    }
    __syncthreads();
    const float c0 = gg0 / r0[0];
    const float c1 = gg1 / r1[0];

    for (int d = tid; d < D_; d += 256) {
        float c = c0 * expf(s0[d] - m0) + c1 * expf(s1[d] - m1);
        if (c == 0.f) c = 2.2204460492503131e-16f;
        out[(size_t)b * D_ + d] = logf(c);
    }
}

// ---------------- launch --------------------------------------------------------
extern "C" void kernel_launch(void* const* d_in, const int* in_sizes, int n_in,
                              void* d_out, int out_size)
{
    const float* x    = (const float*)d_in[0];
    const float* wg   = (const float*)d_in[1];
    const float* fc1w = (const float*)d_in[2];
    const float* fc1b = (const float*)d_in[3];
    const float* fc2w = (const float*)d_in[4];
    const float* fc2b = (const float*)d_in[5];
    float* out = (float*)d_out;

    gating_kernel<<<B_ / 8, 256>>>(x, wg);
    expert_stats_kernel<<<E_, 256>>>();
    scan_loss_kernel<<<1, 32>>>(out);
    scatter_kernel<<<(NSLOT + 255) / 256, 256>>>();

    gemm_mma<H_, D_, true><<<dim3(RMAX / 128, H_ / 128), 256>>>(x, fc1w, fc1b);
    gemm_mma<D_, H_, false><<<dim3(RMAX / 128, D_ / 128), 256>>>(nullptr, fc2w, fc2b);

    combine_kernel<<<B_, 256>>>(out);
}

// round 5
// speedup vs baseline: 6.7503x; 1.3815x over previous
#include <cuda_runtime.h>
#include <cuda_fp16.h>
#include <math.h>
#include <stdint.h>

#define B_    8192
#define D_    1024
#define H_    4096
#define E_    8
#define NSLOT (B_ * 2)
#define RMAX  17408   // 16384 + 8*128 tile padding

// ---------------- scratch (device globals: allocation-free) ----------------
__device__ __align__(128) __half g_h[(size_t)RMAX * H_];     // gelu(fc1), fp16
__device__ __align__(128) float  g_o[(size_t)RMAX * D_];
__device__ __align__(128) __half g_xh[(size_t)B_ * D_];      // x in fp16
__device__ __align__(128) __half g_w1h[(size_t)E_ * H_ * D_];
__device__ __align__(128) __half g_w2h[(size_t)E_ * D_ * H_];
__device__ int   g_tok[RMAX];
__device__ int   g_pos[NSLOT];
__device__ int   g_eidx[NSLOT];
__device__ float g_gval[NSLOT];
__device__ int   g_cnt[E_];
__device__ int   g_cur[E_];
__device__ int   g_off[E_ + 1];
__device__ float g_imp[E_];

// ---------------- helpers ----------------------------------------------------
__device__ __forceinline__ uint32_t smem_u32(const void* p) {
    uint32_t a;
    asm("{ .reg .u64 t; cvta.to.shared.u64 t, %1; cvt.u32.u64 %0, t; }" : "=r"(a) : "l"(p));
    return a;
}
__device__ __forceinline__ void ldmx4(uint32_t& r0, uint32_t& r1, uint32_t& r2, uint32_t& r3,
                                      uint32_t addr) {
    asm volatile("ldmatrix.sync.aligned.m8n8.x4.shared.b16 {%0,%1,%2,%3}, [%4];"
                 : "=r"(r0), "=r"(r1), "=r"(r2), "=r"(r3) : "r"(addr));
}
__device__ __forceinline__ void mma16816(float* c, const uint32_t* a, uint32_t b0, uint32_t b1) {
    asm volatile("mma.sync.aligned.m16n8k16.row.col.f32.f16.f16.f32 "
                 "{%0,%1,%2,%3}, {%4,%5,%6,%7}, {%8,%9}, {%0,%1,%2,%3};"
                 : "+f"(c[0]), "+f"(c[1]), "+f"(c[2]), "+f"(c[3])
                 : "r"(a[0]), "r"(a[1]), "r"(a[2]), "r"(a[3]), "r"(b0), "r"(b1));
}

// ---------------- 0) fp32 -> fp16 conversion ---------------------------------
__global__ void cvt_f2h(const float4* __restrict__ src, uint4* __restrict__ dst, int n8)
{
    int i = blockIdx.x * blockDim.x + threadIdx.x;
    if (i < n8) {
        float4 a = __ldg(&src[2 * i]);
        float4 b = __ldg(&src[2 * i + 1]);
        __half2 h0 = __floats2half2_rn(a.x, a.y);
        __half2 h1 = __floats2half2_rn(a.z, a.w);
        __half2 h2 = __floats2half2_rn(b.x, b.y);
        __half2 h3 = __floats2half2_rn(b.z, b.w);
        dst[i] = make_uint4(*(uint32_t*)&h0, *(uint32_t*)&h1,
                            *(uint32_t*)&h2, *(uint32_t*)&h3);
    }
}

// ---------------- 1) gating --------------------------------------------------
__global__ void gating_kernel(const float* __restrict__ x,
                              const float* __restrict__ wg)
{
    __shared__ float ws[E_ * D_];
    for (int i = threadIdx.x; i < E_ * D_; i += blockDim.x) ws[i] = wg[i];
    __syncthreads();

    const int warp = threadIdx.x >> 5, lane = threadIdx.x & 31;
    const int b = blockIdx.x * 8 + warp;
    const float* xr = x + (size_t)b * D_;

    float acc[E_];
#pragma unroll
    for (int e = 0; e < E_; e++) acc[e] = 0.f;
    for (int d = lane; d < D_; d += 32) {
        float xv = xr[d];
#pragma unroll
        for (int e = 0; e < E_; e++) acc[e] = fmaf(xv, ws[e * D_ + d], acc[e]);
    }
#pragma unroll
    for (int e = 0; e < E_; e++) {
#pragma unroll
        for (int o = 16; o; o >>= 1) acc[e] += __shfl_down_sync(0xffffffffu, acc[e], o);
    }
    if (lane == 0) {
        int i0 = 0; float v0 = acc[0];
#pragma unroll
        for (int e = 1; e < E_; e++) if (acc[e] > v0) { v0 = acc[e]; i0 = e; }
        int i1 = -1; float v1 = -INFINITY;
#pragma unroll
        for (int e = 0; e < E_; e++) if (e != i0 && acc[e] > v1) { v1 = acc[e]; i1 = e; }
        float t  = expf(v1 - v0);
        float gA = 1.f / (1.f + t);
        float gB = t / (1.f + t);
        g_eidx[b * 2 + 0] = i0;  g_eidx[b * 2 + 1] = i1;
        g_gval[b * 2 + 0] = gA;  g_gval[b * 2 + 1] = gB;
    }
}

// ---------------- 2) per-expert stats ----------------------------------------
__global__ void expert_stats_kernel()
{
    const int e = blockIdx.x;
    const int tid = threadIdx.x;
    float imp = 0.f; int cnt = 0;
    for (int i = tid; i < NSLOT; i += 256)
        if (g_eidx[i] == e) { imp += g_gval[i]; cnt++; }
    __shared__ float simp[256];
    __shared__ int   scnt[256];
    simp[tid] = imp; scnt[tid] = cnt;
    __syncthreads();
    for (int s = 128; s; s >>= 1) {
        if (tid < s) { simp[tid] += simp[tid + s]; scnt[tid] += scnt[tid + s]; }
        __syncthreads();
    }
    if (tid == 0) { g_imp[e] = simp[0]; g_cnt[e] = scnt[0]; }
}

// ---------------- 3) scan + loss ----------------------------------------------
__global__ void scan_loss_kernel(float* __restrict__ out)
{
    if (threadIdx.x == 0 && blockIdx.x == 0) {
        int off = 0;
        for (int e = 0; e < E_; e++) {
            g_off[e] = off; g_cur[e] = off;
            off += ((g_cnt[e] + 127) >> 7) << 7;
        }
        g_off[E_] = off;
        float mi = 0.f, ml = 0.f;
        for (int e = 0; e < E_; e++) { mi += g_imp[e]; ml += (float)g_cnt[e]; }
        mi *= (1.f / E_); ml *= (1.f / E_);
        float vi = 0.f, vl = 0.f;
        for (int e = 0; e < E_; e++) {
            float di = g_imp[e] - mi;        vi += di * di;
            float dl = (float)g_cnt[e] - ml; vl += dl * dl;
        }
        vi *= (1.f / (E_ - 1)); vl *= (1.f / (E_ - 1));
        out[(size_t)B_ * D_] = (vi / (mi * mi + 1e-10f) + vl / (ml * ml + 1e-10f)) * 0.01f;
    }
}

// ---------------- 4) scatter ---------------------------------------------------
__global__ void scatter_kernel()
{
    int i = blockIdx.x * blockDim.x + threadIdx.x;
    if (i < NSLOT) {
        int e = g_eidx[i];
        int pos = atomicAdd(&g_cur[e], 1);
        g_tok[pos] = i >> 1;
        g_pos[i] = pos;
    }
}

// ---------------- 5/6) grouped GEMM, mma.sync fp16, K-step 64 -----------------
// CTA tile 128x128, K-step 64. Warp grid 4(m) x 2(n), warp tile 32x64.
// SMEM padded row stride 72 halves (144B = 9x16B, 9 coprime 8) -> conflict-free.
#define LDS_ 72

template<int NFULL, int KDIM, bool PH1>
__global__ __launch_bounds__(256, 2)
void gemm_mma(const __half* __restrict__ A, const __half* __restrict__ W,
              const float* __restrict__ bias)
{
    __shared__ __half As[128 * LDS_];
    __shared__ __half Bs[128 * LDS_];

    const int row0 = blockIdx.x * 128;
    if (row0 >= g_off[E_]) return;

    int e = 0;
#pragma unroll
    for (int i = 0; i < E_; i++) if (row0 >= g_off[i + 1]) e = i + 1;
    const int rowEnd = g_off[e] + g_cnt[e];

    const int tid = threadIdx.x;
    const int w = tid >> 5, lane = tid & 31;
    const int wm = w & 3, wn = w >> 2;
    const int n0 = blockIdx.y * 128;
    const __half* We = W + (size_t)e * NFULL * KDIM;

    // per-thread global-load coords: idx = tid + i*256 -> row=idx>>3, chunk=idx&7
    const __half* pB[4];
    const __half* pA[4];
    uint32_t sOff[4];
#pragma unroll
    for (int i = 0; i < 4; i++) {
        int idx = tid + i * 256;
        int row = idx >> 3, q = idx & 7;
        sOff[i] = row * LDS_ + q * 8;                 // halves
        pB[i] = We + (size_t)(n0 + row) * KDIM + q * 8;
        if (PH1) {
            int tok = g_tok[row0 + row];
            pA[i] = A + (size_t)tok * KDIM + q * 8;
        } else {
            pA[i] = A + (size_t)(row0 + row) * KDIM + q * 8;
        }
    }

    float acc[2][8][4];
#pragma unroll
    for (int a = 0; a < 2; a++)
#pragma unroll
        for (int b = 0; b < 8; b++)
#pragma unroll
            for (int c = 0; c < 4; c++) acc[a][b][c] = 0.f;

    // prefetch regs (16B per chunk)
    uint4 fB[4], fA[4];
#pragma unroll
    for (int i = 0; i < 4; i++) {
        fB[i] = __ldg((const uint4*)pB[i]);
        fA[i] = __ldg((const uint4*)pA[i]);
    }

    const uint32_t sbA = smem_u32(&As[0]);
    const uint32_t sbB = smem_u32(&Bs[0]);

    const int NC = KDIM / 64;
    for (int c = 0; c < NC; c++) {
        __syncthreads();
#pragma unroll
        for (int i = 0; i < 4; i++) {
            *(uint4*)&Bs[sOff[i]] = fB[i];
            *(uint4*)&As[sOff[i]] = fA[i];
        }
        __syncthreads();

        if (c + 1 < NC) {
            int k1 = (c + 1) * 64;
#pragma unroll
            for (int i = 0; i < 4; i++) {
                fB[i] = __ldg((const uint4*)(pB[i] + k1));
                fA[i] = __ldg((const uint4*)(pA[i] + k1));
            }
        }

#pragma unroll
        for (int ks = 0; ks < 4; ks++) {
            const int kk = ks * 16;
            uint32_t aF[2][4];
            uint32_t aoff = ((wm * 32 + (lane & 15)) * LDS_ + kk + ((lane >> 4) << 3)) * 2;
#pragma unroll
            for (int mf = 0; mf < 2; mf++)
                ldmx4(aF[mf][0], aF[mf][1], aF[mf][2], aF[mf][3], sbA + aoff + mf * 16 * LDS_ * 2);

            uint32_t boff = ((wn * 64 + ((lane >> 4) << 3) + (lane & 7)) * LDS_
                             + kk + (((lane >> 3) & 1) << 3)) * 2;
#pragma unroll
            for (int j2 = 0; j2 < 4; j2++) {
                uint32_t bf[4];
                ldmx4(bf[0], bf[1], bf[2], bf[3], sbB + boff + j2 * 16 * LDS_ * 2);
#pragma unroll
                for (int mf = 0; mf < 2; mf++) {
#pragma unroll
                    for (int nf = 0; nf < 2; nf++)
                        mma16816(acc[mf][j2 * 2 + nf], aF[mf], bf[2 * nf], bf[2 * nf + 1]);
                }
            }
        }
    }

    // ---- epilogue ----
    const int g = lane >> 2, cpair = lane & 3;
#pragma unroll
    for (int mf = 0; mf < 2; mf++) {
        int rA = row0 + wm * 32 + mf * 16 + g;
        int rB = rA + 8;
        bool vA = rA < rowEnd, vB = rB < rowEnd;
#pragma unroll
        for (int nf = 0; nf < 8; nf++) {
            int col = n0 + wn * 64 + nf * 8 + 2 * cpair;
            float b0 = __ldg(&bias[(size_t)e * NFULL + col]);
            float b1 = __ldg(&bias[(size_t)e * NFULL + col + 1]);
            float* cc = acc[mf][nf];
            if (PH1) {
#pragma unroll
                for (int half = 0; half < 2; half++) {
                    bool v = half ? vB : vA;
                    if (!v) continue;
                    int r = half ? rB : rA;
                    float v0 = cc[half * 2 + 0] + b0;
                    float v1 = cc[half * 2 + 1] + b1;
                    v0 = 0.5f * v0 * (1.0f + erff(v0 * 0.7071067811865476f));
                    v1 = 0.5f * v1 * (1.0f + erff(v1 * 0.7071067811865476f));
                    __half2 hw = __floats2half2_rn(v0, v1);
                    *(uint32_t*)&g_h[(size_t)r * H_ + col] = *(uint32_t*)&hw;
                }
            } else {
                if (vA) *(float2*)&g_o[(size_t)rA * D_ + col] = make_float2(cc[0] + b0, cc[1] + b1);
                if (vB) *(float2*)&g_o[(size_t)rB * D_ + col] = make_float2(cc[2] + b0, cc[3] + b1);
            }
        }
    }
}

// ---------------- 7) dual softmax + combine + log -----------------------------
__global__ void combine_kernel(float* __restrict__ out)
{
    __shared__ float s0[D_], s1[D_];
    __shared__ float r0[8], r1[8];

    const int b = blockIdx.x;
    const int tid = threadIdx.x;
    const int lane = tid & 31, warp = tid >> 5;

    const int   p0 = g_pos[b * 2 + 0], p1 = g_pos[b * 2 + 1];
    const float gg0 = g_gval[b * 2 + 0], gg1 = g_gval[b * 2 + 1];
    const float* q0 = g_o + (size_t)p0 * D_;
    const float* q1 = g_o + (size_t)p1 * D_;

    float m0 = -INFINITY, m1 = -INFINITY;
    for (int d = tid; d < D_; d += 256) {
        float v0 = q0[d], v1 = q1[d];
        s0[d] = v0; s1[d] = v1;
        m0 = fmaxf(m0, v0); m1 = fmaxf(m1, v1);
    }
#pragma unroll
    for (int o = 16; o; o >>= 1) {
        m0 = fmaxf(m0, __shfl_down_sync(0xffffffffu, m0, o));
        m1 = fmaxf(m1, __shfl_down_sync(0xffffffffu, m1, o));
    }
    if (lane == 0) { r0[warp] = m0; r1[warp] = m1; }
    __syncthreads();
    if (tid == 0) {
        float a = r0[0], c = r1[0];
        for (int i = 1; i < 8; i++) { a = fmaxf(a, r0[i]); c = fmaxf(c, r1[i]); }
        r0[0] = a; r1[0] = c;
    }
    __syncthreads();
    m0 = r0[0]; m1 = r1[0];

    float e0 = 0.f, e1 = 0.f;
    for (int d = tid; d < D_; d += 256) {
        e0 += expf(s0[d] - m0);
        e1 += expf(s1[d] - m1);
    }
#pragma unroll
    for (int o = 16; o; o >>= 1) {
        e0 += __shfl_down_sync(0xffffffffu, e0, o);
        e1 += __shfl_down_sync(0xffffffffu, e1, o);
    }
    __syncthreads();
    if (lane == 0) { r0[warp] = e0; r1[warp] = e1; }
    __syncthreads();
    if (tid == 0) {
        float a = 0.f, c = 0.f;
        for (int i = 0; i < 8; i++) { a += r0[i]; c += r1[i]; }
        r0[0] = a; r1[0] = c;
    }
    __syncthreads();
    const float c0 = gg0 / r0[0];
    const float c1 = gg1 / r1[0];

    for (int d = tid; d < D_; d += 256) {
        float c = c0 * expf(s0[d] - m0) + c1 * expf(s1[d] - m1);
        if (c == 0.f) c = 2.2204460492503131e-16f;
        out[(size_t)b * D_ + d] = logf(c);
    }
}

// ---------------- launch --------------------------------------------------------
extern "C" void kernel_launch(void* const* d_in, const int* in_sizes, int n_in,
                              void* d_out, int out_size)
{
    const float* x    = (const float*)d_in[0];
    const float* wg   = (const float*)d_in[1];
    const float* fc1w = (const float*)d_in[2];
    const float* fc1b = (const float*)d_in[3];
    const float* fc2w = (const float*)d_in[4];
    const float* fc2b = (const float*)d_in[5];
    float* out = (float*)d_out;

    __half* xh;  cudaGetSymbolAddress((void**)&xh,  g_xh);
    __half* w1h; cudaGetSymbolAddress((void**)&w1h, g_w1h);
    __half* w2h; cudaGetSymbolAddress((void**)&w2h, g_w2h);

    const int nW = E_ * H_ * D_ / 8;     // 4194304
    const int nX = B_ * D_ / 8;          // 1048576
    cvt_f2h<<<(nX + 255) / 256, 256>>>((const float4*)x,    (uint4*)xh,  nX);
    cvt_f2h<<<(nW + 255) / 256, 256>>>((const float4*)fc1w, (uint4*)w1h, nW);
    cvt_f2h<<<(nW + 255) / 256, 256>>>((const float4*)fc2w, (uint4*)w2h, nW);

    gating_kernel<<<B_ / 8, 256>>>(x, wg);
    expert_stats_kernel<<<E_, 256>>>();
    scan_loss_kernel<<<1, 32>>>(out);
    scatter_kernel<<<(NSLOT + 255) / 256, 256>>>();

    __half* hh; cudaGetSymbolAddress((void**)&hh, g_h);
    gemm_mma<H_, D_, true><<<dim3(RMAX / 128, H_ / 128), 256>>>(xh, w1h, fc1b);
    gemm_mma<D_, H_, false><<<dim3(RMAX / 128, D_ / 128), 256>>>(hh, w2h, fc2b);

    combine_kernel<<<B_, 256>>>(out);
}

// round 6
// speedup vs baseline: 7.2435x; 1.0731x over previous
#include <cuda_runtime.h>
#include <cuda_fp16.h>
#include <math.h>
#include <stdint.h>

#define B_    8192
#define D_    1024
#define H_    4096
#define E_    8
#define NSLOT (B_ * 2)
#define RMAX  17408   // 16384 + 8*128 tile padding

// ---------------- scratch (device globals: allocation-free) ----------------
__device__ __align__(128) __half g_h[(size_t)RMAX * H_];     // gelu(fc1), fp16
__device__ __align__(128) float  g_o[(size_t)RMAX * D_];
__device__ __align__(128) __half g_xh[(size_t)B_ * D_];      // x in fp16
__device__ __align__(128) __half g_w1h[(size_t)E_ * H_ * D_];
__device__ __align__(128) __half g_w2h[(size_t)E_ * D_ * H_];
__device__ int   g_tok[RMAX];
__device__ int   g_pos[NSLOT];
__device__ int   g_eidx[NSLOT];
__device__ float g_gval[NSLOT];
__device__ int   g_cnt[E_];
__device__ int   g_cur[E_];
__device__ int   g_off[E_ + 1];
__device__ float g_imp[E_];

// ---------------- helpers ----------------------------------------------------
__device__ __forceinline__ uint32_t smem_u32(const void* p) {
    uint32_t a;
    asm("{ .reg .u64 t; cvta.to.shared.u64 t, %1; cvt.u32.u64 %0, t; }" : "=r"(a) : "l"(p));
    return a;
}
__device__ __forceinline__ void ldmx4(uint32_t& r0, uint32_t& r1, uint32_t& r2, uint32_t& r3,
                                      uint32_t addr) {
    asm volatile("ldmatrix.sync.aligned.m8n8.x4.shared.b16 {%0,%1,%2,%3}, [%4];"
                 : "=r"(r0), "=r"(r1), "=r"(r2), "=r"(r3) : "r"(addr));
}
__device__ __forceinline__ void mma16816(float* c, const uint32_t* a, uint32_t b0, uint32_t b1) {
    asm volatile("mma.sync.aligned.m16n8k16.row.col.f32.f16.f16.f32 "
                 "{%0,%1,%2,%3}, {%4,%5,%6,%7}, {%8,%9}, {%0,%1,%2,%3};"
                 : "+f"(c[0]), "+f"(c[1]), "+f"(c[2]), "+f"(c[3])
                 : "r"(a[0]), "r"(a[1]), "r"(a[2]), "r"(a[3]), "r"(b0), "r"(b1));
}
__device__ __forceinline__ void cp16(uint32_t dst, const void* src) {
    asm volatile("cp.async.cg.shared.global [%0], [%1], 16;" :: "r"(dst), "l"(src));
}
__device__ __forceinline__ void cp_commit() {
    asm volatile("cp.async.commit_group;" ::: "memory");
}
__device__ __forceinline__ void cp_wait0() {
    asm volatile("cp.async.wait_group 0;" ::: "memory");
}

// ---------------- 0) fp32 -> fp16 conversion ---------------------------------
__global__ void cvt_f2h(const float4* __restrict__ src, uint4* __restrict__ dst, int n8)
{
    int i = blockIdx.x * blockDim.x + threadIdx.x;
    if (i < n8) {
        float4 a = __ldg(&src[2 * i]);
        float4 b = __ldg(&src[2 * i + 1]);
        __half2 h0 = __floats2half2_rn(a.x, a.y);
        __half2 h1 = __floats2half2_rn(a.z, a.w);
        __half2 h2 = __floats2half2_rn(b.x, b.y);
        __half2 h3 = __floats2half2_rn(b.z, b.w);
        dst[i] = make_uint4(*(uint32_t*)&h0, *(uint32_t*)&h1,
                            *(uint32_t*)&h2, *(uint32_t*)&h3);
    }
}

// ---------------- 1) gating --------------------------------------------------
__global__ void gating_kernel(const float* __restrict__ x,
                              const float* __restrict__ wg)
{
    __shared__ float ws[E_ * D_];
    for (int i = threadIdx.x; i < E_ * D_; i += blockDim.x) ws[i] = wg[i];
    __syncthreads();

    const int warp = threadIdx.x >> 5, lane = threadIdx.x & 31;
    const int b = blockIdx.x * 8 + warp;
    const float* xr = x + (size_t)b * D_;

    float acc[E_];
#pragma unroll
    for (int e = 0; e < E_; e++) acc[e] = 0.f;
    for (int d = lane; d < D_; d += 32) {
        float xv = xr[d];
#pragma unroll
        for (int e = 0; e < E_; e++) acc[e] = fmaf(xv, ws[e * D_ + d], acc[e]);
    }
#pragma unroll
    for (int e = 0; e < E_; e++) {
#pragma unroll
        for (int o = 16; o; o >>= 1) acc[e] += __shfl_down_sync(0xffffffffu, acc[e], o);
    }
    if (lane == 0) {
        int i0 = 0; float v0 = acc[0];
#pragma unroll
        for (int e = 1; e < E_; e++) if (acc[e] > v0) { v0 = acc[e]; i0 = e; }
        int i1 = -1; float v1 = -INFINITY;
#pragma unroll
        for (int e = 0; e < E_; e++) if (e != i0 && acc[e] > v1) { v1 = acc[e]; i1 = e; }
        float t  = expf(v1 - v0);
        float gA = 1.f / (1.f + t);
        float gB = t / (1.f + t);
        g_eidx[b * 2 + 0] = i0;  g_eidx[b * 2 + 1] = i1;
        g_gval[b * 2 + 0] = gA;  g_gval[b * 2 + 1] = gB;
    }
}

// ---------------- 2) per-expert stats ----------------------------------------
__global__ void expert_stats_kernel()
{
    const int e = blockIdx.x;
    const int tid = threadIdx.x;
    float imp = 0.f; int cnt = 0;
    for (int i = tid; i < NSLOT; i += 256)
        if (g_eidx[i] == e) { imp += g_gval[i]; cnt++; }
    __shared__ float simp[256];
    __shared__ int   scnt[256];
    simp[tid] = imp; scnt[tid] = cnt;
    __syncthreads();
    for (int s = 128; s; s >>= 1) {
        if (tid < s) { simp[tid] += simp[tid + s]; scnt[tid] += scnt[tid + s]; }
        __syncthreads();
    }
    if (tid == 0) { g_imp[e] = simp[0]; g_cnt[e] = scnt[0]; }
}

// ---------------- 3) scan + loss ----------------------------------------------
__global__ void scan_loss_kernel(float* __restrict__ out)
{
    if (threadIdx.x == 0 && blockIdx.x == 0) {
        int off = 0;
        for (int e = 0; e < E_; e++) {
            g_off[e] = off; g_cur[e] = off;
            off += ((g_cnt[e] + 127) >> 7) << 7;
        }
        g_off[E_] = off;
        float mi = 0.f, ml = 0.f;
        for (int e = 0; e < E_; e++) { mi += g_imp[e]; ml += (float)g_cnt[e]; }
        mi *= (1.f / E_); ml *= (1.f / E_);
        float vi = 0.f, vl = 0.f;
        for (int e = 0; e < E_; e++) {
            float di = g_imp[e] - mi;        vi += di * di;
            float dl = (float)g_cnt[e] - ml; vl += dl * dl;
        }
        vi *= (1.f / (E_ - 1)); vl *= (1.f / (E_ - 1));
        out[(size_t)B_ * D_] = (vi / (mi * mi + 1e-10f) + vl / (ml * ml + 1e-10f)) * 0.01f;
    }
}

// ---------------- 4) scatter ---------------------------------------------------
__global__ void scatter_kernel()
{
    int i = blockIdx.x * blockDim.x + threadIdx.x;
    if (i < NSLOT) {
        int e = g_eidx[i];
        int pos = atomicAdd(&g_cur[e], 1);
        g_tok[pos] = i >> 1;
        g_pos[i] = pos;
    }
}

// ---------------- 5/6) grouped GEMM, cp.async double-buffered -----------------
// CTA tile 128x128, K-step 64, 2-stage pipeline. Warp grid 4x2, warp tile 32x64.
// SMEM padded row stride 72 halves (144B = 9x16B) -> ldmatrix conflict-free.
#define LDS_ 72
#define STG_HALVES (128 * LDS_)           // per matrix per stage
#define STG_BYTES  (2 * STG_HALVES * 2)   // A + B, bytes  (36864)
#define SMEM_TOT   (2 * STG_BYTES)        // 73728

template<int NFULL, int KDIM, bool PH1>
__global__ __launch_bounds__(256, 2)
void gemm_mma(const __half* __restrict__ A, const __half* __restrict__ W,
              const float* __restrict__ bias)
{
    extern __shared__ __half smem[];

    const int row0 = blockIdx.x * 128;
    if (row0 >= g_off[E_]) return;

    int e = 0;
#pragma unroll
    for (int i = 0; i < E_; i++) if (row0 >= g_off[i + 1]) e = i + 1;
    const int rowEnd = g_off[e] + g_cnt[e];

    const int tid = threadIdx.x;
    const int w = tid >> 5, lane = tid & 31;
    const int wm = w & 3, wn = w >> 2;
    const int n0 = blockIdx.y * 128;
    const __half* We = W + (size_t)e * NFULL * KDIM;

    const uint32_t sb = smem_u32(smem);

    // per-thread load coords: idx = tid + i*256 -> row=idx>>3, chunk=idx&7
    const __half* pB[4];
    const __half* pA[4];
    uint32_t sOffB[4];   // byte offset within a stage's A (or B) matrix
#pragma unroll
    for (int i = 0; i < 4; i++) {
        int idx = tid + i * 256;
        int row = idx >> 3, q = idx & 7;
        sOffB[i] = (row * LDS_ + q * 8) * 2;
        pB[i] = We + (size_t)(n0 + row) * KDIM + q * 8;
        if (PH1) {
            int tok = g_tok[row0 + row];
            pA[i] = A + (size_t)tok * KDIM + q * 8;
        } else {
            pA[i] = A + (size_t)(row0 + row) * KDIM + q * 8;
        }
    }

    float acc[2][8][4];
#pragma unroll
    for (int a = 0; a < 2; a++)
#pragma unroll
        for (int b = 0; b < 8; b++)
#pragma unroll
            for (int c = 0; c < 4; c++) acc[a][b][c] = 0.f;

    const int NC = KDIM / 64;

    // prologue: stage 0
    {
        uint32_t dA = sb, dB = sb + STG_HALVES * 2;
#pragma unroll
        for (int i = 0; i < 4; i++) {
            cp16(dA + sOffB[i], pA[i]);
            cp16(dB + sOffB[i], pB[i]);
        }
        cp_commit();
    }

    for (int c = 0; c < NC; c++) {
        cp_wait0();
        __syncthreads();

        if (c + 1 < NC) {
            const int k1 = (c + 1) * 64;
            uint32_t base = sb + ((c + 1) & 1) * STG_BYTES;
            uint32_t dA = base, dB = base + STG_HALVES * 2;
#pragma unroll
            for (int i = 0; i < 4; i++) {
                cp16(dA + sOffB[i], pA[i] + k1);
                cp16(dB + sOffB[i], pB[i] + k1);
            }
            cp_commit();
        }

        const uint32_t sbA = sb + (c & 1) * STG_BYTES;
        const uint32_t sbB = sbA + STG_HALVES * 2;

#pragma unroll
        for (int ks = 0; ks < 4; ks++) {
            const int kk = ks * 16;
            uint32_t aF[2][4];
            uint32_t aoff = ((wm * 32 + (lane & 15)) * LDS_ + kk + ((lane >> 4) << 3)) * 2;
#pragma unroll
            for (int mf = 0; mf < 2; mf++)
                ldmx4(aF[mf][0], aF[mf][1], aF[mf][2], aF[mf][3], sbA + aoff + mf * 16 * LDS_ * 2);

            uint32_t boff = ((wn * 64 + ((lane >> 4) << 3) + (lane & 7)) * LDS_
                             + kk + (((lane >> 3) & 1) << 3)) * 2;
#pragma unroll
            for (int j2 = 0; j2 < 4; j2++) {
                uint32_t bf[4];
                ldmx4(bf[0], bf[1], bf[2], bf[3], sbB + boff + j2 * 16 * LDS_ * 2);
#pragma unroll
                for (int mf = 0; mf < 2; mf++) {
#pragma unroll
                    for (int nf = 0; nf < 2; nf++)
                        mma16816(acc[mf][j2 * 2 + nf], aF[mf], bf[2 * nf], bf[2 * nf + 1]);
                }
            }
        }
    }

    // ---- epilogue ----
    const int g = lane >> 2, cpair = lane & 3;
#pragma unroll
    for (int mf = 0; mf < 2; mf++) {
        int rA = row0 + wm * 32 + mf * 16 + g;
        int rB = rA + 8;
        bool vA = rA < rowEnd, vB = rB < rowEnd;
#pragma unroll
        for (int nf = 0; nf < 8; nf++) {
            int col = n0 + wn * 64 + nf * 8 + 2 * cpair;
            float b0 = __ldg(&bias[(size_t)e * NFULL + col]);
            float b1 = __ldg(&bias[(size_t)e * NFULL + col + 1]);
            float* cc = acc[mf][nf];
            if (PH1) {
#pragma unroll
                for (int half = 0; half < 2; half++) {
                    bool v = half ? vB : vA;
                    if (!v) continue;
                    int r = half ? rB : rA;
                    float v0 = cc[half * 2 + 0] + b0;
                    float v1 = cc[half * 2 + 1] + b1;
                    v0 = 0.5f * v0 * (1.0f + erff(v0 * 0.7071067811865476f));
                    v1 = 0.5f * v1 * (1.0f + erff(v1 * 0.7071067811865476f));
                    __half2 hw = __floats2half2_rn(v0, v1);
                    *(uint32_t*)&g_h[(size_t)r * H_ + col] = *(uint32_t*)&hw;
                }
            } else {
                if (vA) *(float2*)&g_o[(size_t)rA * D_ + col] = make_float2(cc[0] + b0, cc[1] + b1);
                if (vB) *(float2*)&g_o[(size_t)rB * D_ + col] = make_float2(cc[2] + b0, cc[3] + b1);
            }
        }
    }
}

// ---------------- 7) dual softmax + combine + log -----------------------------
__global__ void combine_kernel(float* __restrict__ out)
{
    __shared__ float s0[D_], s1[D_];
    __shared__ float r0[8], r1[8];

    const int b = blockIdx.x;
    const int tid = threadIdx.x;
    const int lane = tid & 31, warp = tid >> 5;

    const int   p0 = g_pos[b * 2 + 0], p1 = g_pos[b * 2 + 1];
    const float gg0 = g_gval[b * 2 + 0], gg1 = g_gval[b * 2 + 1];
    const float* q0 = g_o + (size_t)p0 * D_;
    const float* q1 = g_o + (size_t)p1 * D_;

    float m0 = -INFINITY, m1 = -INFINITY;
    for (int d = tid; d < D_; d += 256) {
        float v0 = q0[d], v1 = q1[d];
        s0[d] = v0; s1[d] = v1;
        m0 = fmaxf(m0, v0); m1 = fmaxf(m1, v1);
    }
#pragma unroll
    for (int o = 16; o; o >>= 1) {
        m0 = fmaxf(m0, __shfl_down_sync(0xffffffffu, m0, o));
        m1 = fmaxf(m1, __shfl_down_sync(0xffffffffu, m1, o));
    }
    if (lane == 0) { r0[warp] = m0; r1[warp] = m1; }
    __syncthreads();
    if (tid == 0) {
        float a = r0[0], c = r1[0];
        for (int i = 1; i < 8; i++) { a = fmaxf(a, r0[i]); c = fmaxf(c, r1[i]); }
        r0[0] = a; r1[0] = c;
    }
    __syncthreads();
    m0 = r0[0]; m1 = r1[0];

    float e0 = 0.f, e1 = 0.f;
    for (int d = tid; d < D_; d += 256) {
        e0 += expf(s0[d] - m0);
        e1 += expf(s1[d] - m1);
    }
#pragma unroll
    for (int o = 16; o; o >>= 1) {
        e0 += __shfl_down_sync(0xffffffffu, e0, o);
        e1 += __shfl_down_sync(0xffffffffu, e1, o);
    }
    __syncthreads();
    if (lane == 0) { r0[warp] = e0; r1[warp] = e1; }
    __syncthreads();
    if (tid == 0) {
        float a = 0.f, c = 0.f;
        for (int i = 0; i < 8; i++) { a += r0[i]; c += r1[i]; }
        r0[0] = a; r1[0] = c;
    }
    __syncthreads();
    const float c0 = gg0 / r0[0];
    const float c1 = gg1 / r1[0];

    for (int d = tid; d < D_; d += 256) {
        float c = c0 * expf(s0[d] - m0) + c1 * expf(s1[d] - m1);
        if (c == 0.f) c = 2.2204460492503131e-16f;
        out[(size_t)b * D_ + d] = logf(c);
    }
}

// ---------------- launch --------------------------------------------------------
extern "C" void kernel_launch(void* const* d_in, const int* in_sizes, int n_in,
                              void* d_out, int out_size)
{
    const float* x    = (const float*)d_in[0];
    const float* wg   = (const float*)d_in[1];
    const float* fc1w = (const float*)d_in[2];
    const float* fc1b = (const float*)d_in[3];
    const float* fc2w = (const float*)d_in[4];
    const float* fc2b = (const float*)d_in[5];
    float* out = (float*)d_out;

    __half* xh;  cudaGetSymbolAddress((void**)&xh,  g_xh);
    __half* w1h; cudaGetSymbolAddress((void**)&w1h, g_w1h);
    __half* w2h; cudaGetSymbolAddress((void**)&w2h, g_w2h);
    __half* hh;  cudaGetSymbolAddress((void**)&hh,  g_h);

    cudaFuncSetAttribute(gemm_mma<H_, D_, true>,
                         cudaFuncAttributeMaxDynamicSharedMemorySize, SMEM_TOT);
    cudaFuncSetAttribute(gemm_mma<D_, H_, false>,
                         cudaFuncAttributeMaxDynamicSharedMemorySize, SMEM_TOT);

    const int nW = E_ * H_ * D_ / 8;     // 4194304
    const int nX = B_ * D_ / 8;          // 1048576
    cvt_f2h<<<(nX + 255) / 256, 256>>>((const float4*)x,    (uint4*)xh,  nX);
    cvt_f2h<<<(nW + 255) / 256, 256>>>((const float4*)fc1w, (uint4*)w1h, nW);
    cvt_f2h<<<(nW + 255) / 256, 256>>>((const float4*)fc2w, (uint4*)w2h, nW);

    gating_kernel<<<B_ / 8, 256>>>(x, wg);
    expert_stats_kernel<<<E_, 256>>>();
    scan_loss_kernel<<<1, 32>>>(out);
    scatter_kernel<<<(NSLOT + 255) / 256, 256>>>();

    gemm_mma<H_, D_, true><<<dim3(RMAX / 128, H_ / 128), 256, SMEM_TOT>>>(xh, w1h, fc1b);
    gemm_mma<D_, H_, false><<<dim3(RMAX / 128, D_ / 128), 256, SMEM_TOT>>>(hh, w2h, fc2b);

    combine_kernel<<<B_, 256>>>(out);
}